// round 16
// baseline (speedup 1.0000x reference)
#include <cuda_runtime.h>
#include <cuda_bf16.h>
#include <cstdint>

// ---------------------------------------------------------------------------
// TrivialGNN: 3-layer GCN.
// Per GCN layer:
//   s = X @ W                     (tensor-core bf16x3 GEMM, unscaled)
//   h[c] = relu( dinv[c] * (dinv[c]*s[c] + sum_{r->c} dinv[r]*s[r]) + b )
// dinv applied during aggregation so the layer-1 GEMM is independent of the
// CSR build and overlaps it on a second stream (graph fork/join via events).
// GEMM: SMEM holds operands in *fragment order* -- each lane's 4 A regs are
// one contiguous uint4, its 2 B regs one uint2 -> inner loop is 16 LDS issues
// vs 48 HMMA per k16 step (tensor-bound instead of LDS-bound).
// CSR build: histogram with rank capture, 2-kernel multi-block scan (block
// sums; then per-block offset reduce + local scan fused), atomic-free place.
// ---------------------------------------------------------------------------

#define MAX_N 50000
#define MAX_E 640000
#define SCAN_B 256
#define MAX_SB 256

__device__ float g_dinv[MAX_N];        // rsqrt(in-degree incl. self loop)
__device__ float g_s  [MAX_N * 128];   // XW (gather source, unscaled)
__device__ float g_h  [MAX_N * 128];   // layer output
__device__ int   g_cnt[MAX_N];         // per-destination edge count
__device__ int   g_off[MAX_N + 1];     // CSR offsets
__device__ int   g_rank[MAX_E];        // per-edge rank within its destination
__device__ int   g_csr[MAX_E];         // source node per CSR slot
__device__ int   g_bsum[MAX_SB];       // per-block count sums
__device__ int   g_is64;               // edge_index dtype flag

// ----------------------- zero counts + dtype detect -------------------------
__global__ void zero_detect_kernel(const int* __restrict__ ei, int n) {
    int i = blockIdx.x * blockDim.x + threadIdx.x;
    if (i < n) g_cnt[i] = 0;
    if (blockIdx.x == 0 && threadIdx.x < 32) {
        long long s = 0;
#pragma unroll
        for (int k = 0; k < 32; k++)
            s += (long long)__ldg(ei + 2 * (threadIdx.x * 32 + k) + 1);
#pragma unroll
        for (int o = 16; o > 0; o >>= 1)
            s += __shfl_down_sync(0xffffffffu, s, o);
        if (threadIdx.x == 0) g_is64 = (s == 0) ? 1 : 0;
    }
}

__device__ __forceinline__ void load_edge(const void* ei, int E, int e,
                                          int& r, int& c) {
    if (g_is64) {
        const long long* p = (const long long*)ei;
        r = (int)__ldg(p + e);
        c = (int)__ldg(p + E + e);
    } else {
        const int* p = (const int*)ei;
        r = __ldg(p + e);
        c = __ldg(p + E + e);
    }
}

// ------------------------------ CSR build ----------------------------------
__global__ void hist_kernel(const void* __restrict__ ei, int E) {
    int e = blockIdx.x * blockDim.x + threadIdx.x;
    if (e >= E) return;
    int r, c; load_edge(ei, E, e, r, c);
    g_rank[e] = atomicAdd(&g_cnt[c], 1);
}

// ---- scan phase 1: per-block reduction of counts (+ dinv on the way) ------
__global__ __launch_bounds__(SCAN_B) void scan_blocksum(int n) {
    const int tid  = threadIdx.x;
    const int i    = blockIdx.x * SCAN_B + tid;
    const int lane = tid & 31;
    const int warp = tid >> 5;
    int v = (i < n) ? g_cnt[i] : 0;
    if (i < n) g_dinv[i] = rsqrtf((float)v + 1.0f);   // +1 = self loop
    int s = v;
#pragma unroll
    for (int o = 16; o > 0; o >>= 1) s += __shfl_down_sync(0xffffffffu, s, o);
    __shared__ int sh[SCAN_B / 32];
    if (lane == 0) sh[warp] = s;
    __syncthreads();
    if (tid == 0) {
        int t = 0;
#pragma unroll
        for (int w = 0; w < SCAN_B / 32; w++) t += sh[w];
        g_bsum[blockIdx.x] = t;
    }
}

// ---- scan phase 2 (fused): per-block offset reduce + local exclusive scan --
__global__ __launch_bounds__(SCAN_B) void scan_final(int n) {
    const int tid  = threadIdx.x;
    const int i    = blockIdx.x * SCAN_B + tid;
    const int lane = tid & 31;
    const int warp = tid >> 5;
    __shared__ int shr[SCAN_B / 32];   // for the offset reduction
    __shared__ int shs[SCAN_B / 32];   // for the local scan
    __shared__ int boff_s;

    // block offset = sum of preceding block sums (<= 256 of them)
    int vb = (tid < blockIdx.x) ? g_bsum[tid] : 0;
#pragma unroll
    for (int o = 16; o > 0; o >>= 1) vb += __shfl_down_sync(0xffffffffu, vb, o);
    if (lane == 0) shr[warp] = vb;
    __syncthreads();
    if (tid == 0) {
        int t = 0;
#pragma unroll
        for (int w = 0; w < SCAN_B / 32; w++) t += shr[w];
        boff_s = t;
    }

    // local exclusive scan of this block's counts
    const int v = (i < n) ? g_cnt[i] : 0;
    int x = v;
#pragma unroll
    for (int o = 1; o < 32; o <<= 1) {
        int y = __shfl_up_sync(0xffffffffu, x, o);
        if (lane >= o) x += y;
    }
    if (lane == 31) shs[warp] = x;
    __syncthreads();
    if (tid < SCAN_B / 32) {
        int w = shs[tid];
#pragma unroll
        for (int o = 1; o < SCAN_B / 32; o <<= 1) {
            int y = __shfl_up_sync((1u << (SCAN_B / 32)) - 1u, w, o);
            if (tid >= o) w += y;
        }
        shs[tid] = w;
    }
    __syncthreads();
    const int incl = x + ((warp > 0) ? shs[warp - 1] : 0);
    const int boff = boff_s;
    if (i < n) g_off[i] = boff + incl - v;
    if (blockIdx.x == gridDim.x - 1 && tid == SCAN_B - 1)
        g_off[n] = boff + incl;    // grand total (tail lanes hold zeros)
}

// Atomic-free placement: pos = off[c] + rank[e].
__global__ void fillcsr_kernel(const void* __restrict__ ei, int E) {
    int e = blockIdx.x * blockDim.x + threadIdx.x;
    if (e >= E) return;
    int r, c; load_edge(ei, E, e, r, c);
    g_csr[g_off[c] + __ldg(&g_rank[e])] = r;
}

// --------------------------- bf16x3 tensor GEMM -----------------------------
__device__ __forceinline__ void pack2(float x, float y,
                                      uint32_t& h, uint32_t& l) {
    __nv_bfloat16 hx = __float2bfloat16_rn(x);
    __nv_bfloat16 hy = __float2bfloat16_rn(y);
    float rx = x - __bfloat162float(hx);
    float ry = y - __bfloat162float(hy);
    __nv_bfloat16 lx = __float2bfloat16_rn(rx);
    __nv_bfloat16 ly = __float2bfloat16_rn(ry);
    h = (uint32_t)*(uint16_t*)&hx | ((uint32_t)*(uint16_t*)&hy << 16);
    l = (uint32_t)*(uint16_t*)&lx | ((uint32_t)*(uint16_t*)&ly << 16);
}

#define MMA_BF16(c, a, b)                                                    \
    asm volatile("mma.sync.aligned.m16n8k16.row.col.f32.bf16.bf16.f32 "      \
                 "{%0,%1,%2,%3}, {%4,%5,%6,%7}, {%8,%9}, {%0,%1,%2,%3};"     \
                 : "+f"((c)[0]), "+f"((c)[1]), "+f"((c)[2]), "+f"((c)[3])    \
                 : "r"((a)[0]), "r"((a)[1]), "r"((a)[2]), "r"((a)[3]),       \
                   "r"((b)[0]), "r"((b)[1]))

// C[M,TN] = A[M,128] @ B[128,TN]. 128 x TN block tile, 256 threads (8 warps),
// K=128 staged once in SMEM in FRAGMENT ORDER:
//   A slot (kk, rg, lane) -> uint4 {A[rg16+g][w], A[rg16+g+8][w],
//                                   A[rg16+g][w+4], A[rg16+g+8][w+4]}
//   B slot (kk, cg, lane) -> uint2 {B_word(kk8+tg, col cg8+g),
//                                   B_word(kk8+tg+4, col)}
// where w = kk*8+tg, g = lane>>2, tg = lane&3; words are packed bf16x2 over k.
// FINAL=false: g_s[row] = C[row]      FINAL=true: OUT = C + bias
template<int TN, bool FINAL>
__global__ __launch_bounds__(256, 1) void mma_gemm(
    const float* __restrict__ A, const float* __restrict__ B,
    const float* __restrict__ bias, float* __restrict__ OUT, int M)
{
    constexpr int WM  = (TN == 128) ? 2 : 4;   // warps along M
    constexpr int WN  = 8 / WM;                // warps along N
    constexpr int MT  = 128 / WM / 16;         // m16 tiles per warp
    constexpr int NT  = TN / WN / 8;           // n8 tiles per warp
    constexpr int RPW = 128 / WM;
    constexpr int CPW = TN / WN;
    constexpr int NCG = TN / 8;                // col groups

    extern __shared__ uint32_t smw[];
    uint32_t* A_hi = smw;                      // 8*8*32*4   = 8192 words
    uint32_t* A_lo = A_hi + 8192;
    uint32_t* B_hi = A_lo + 8192;              // 8*NCG*32*2 words
    uint32_t* B_lo = B_hi + 8 * NCG * 32 * 2;

    const int tid    = threadIdx.x;
    const int warpId = tid >> 5;
    const int lane   = tid & 31;
    const int g      = lane >> 2;
    const int tg     = lane & 3;
    const int wm     = warpId % WM;
    const int wn     = warpId / WM;
    const int blockRow = blockIdx.x * 128;

    // ---- stage A in fragment order: 2048 slots ----
#pragma unroll
    for (int it = 0; it < 8; it++) {
        const int s   = tid + it * 256;        // slot id
        const int ls  = s & 31;
        const int rg  = (s >> 5) & 7;
        const int kk  = s >> 8;
        const int gg  = ls >> 2;
        const int tt  = ls & 3;
        const int r0  = blockRow + rg * 16 + gg;
        const int r1  = r0 + 8;
        const int c0  = kk * 16 + 2 * tt;
        float2 z = make_float2(0.f, 0.f);
        float2 v00 = (r0 < M) ? *(const float2*)(A + (size_t)r0 * 128 + c0)     : z;
        float2 v10 = (r1 < M) ? *(const float2*)(A + (size_t)r1 * 128 + c0)     : z;
        float2 v01 = (r0 < M) ? *(const float2*)(A + (size_t)r0 * 128 + c0 + 8) : z;
        float2 v11 = (r1 < M) ? *(const float2*)(A + (size_t)r1 * 128 + c0 + 8) : z;
        uint32_t h0, l0, h1, l1, h2, l2, h3, l3;
        pack2(v00.x, v00.y, h0, l0);
        pack2(v10.x, v10.y, h1, l1);
        pack2(v01.x, v01.y, h2, l2);
        pack2(v11.x, v11.y, h3, l3);
        *(uint4*)&A_hi[(size_t)s * 4] = make_uint4(h0, h1, h2, h3);
        *(uint4*)&A_lo[(size_t)s * 4] = make_uint4(l0, l1, l2, l3);
    }
    // ---- stage B in fragment order: 8*NCG*32 slots ----
#pragma unroll
    for (int it = 0; it < NCG; it++) {
        const int s   = tid + it * 256;
        const int ls  = s & 31;
        const int cg  = (s >> 5) & (NCG - 1);
        const int kk  = s / (32 * NCG);
        const int gg  = ls >> 2;
        const int tt  = ls & 3;
        const int col = cg * 8 + gg;
        const int k0  = kk * 16 + 2 * tt;
        const float b00 = B[(size_t)k0 * TN + col];
        const float b01 = B[(size_t)(k0 + 1) * TN + col];
        const float b10 = B[(size_t)(k0 + 8) * TN + col];
        const float b11 = B[(size_t)(k0 + 9) * TN + col];
        uint32_t h0, l0, h1, l1;
        pack2(b00, b01, h0, l0);
        pack2(b10, b11, h1, l1);
        *(uint2*)&B_hi[(size_t)s * 2] = make_uint2(h0, h1);
        *(uint2*)&B_lo[(size_t)s * 2] = make_uint2(l0, l1);
    }
    __syncthreads();

    float acc[MT][NT][4];
#pragma unroll
    for (int mi = 0; mi < MT; mi++)
#pragma unroll
        for (int ni = 0; ni < NT; ni++)
#pragma unroll
            for (int q = 0; q < 4; q++) acc[mi][ni][q] = 0.0f;

#pragma unroll
    for (int kk = 0; kk < 8; kk++) {
        uint4 ah[MT], al[MT];
#pragma unroll
        for (int mi = 0; mi < MT; mi++) {
            const int rg = wm * MT + mi;
            const size_t base = ((size_t)(kk * 8 + rg) * 32 + lane) * 4;
            ah[mi] = *(uint4*)&A_hi[base];
            al[mi] = *(uint4*)&A_lo[base];
        }
        uint2 bh[NT], bl[NT];
#pragma unroll
        for (int ni = 0; ni < NT; ni++) {
            const int cg = wn * NT + ni;
            const size_t base = ((size_t)(kk * NCG + cg) * 32 + lane) * 2;
            bh[ni] = *(uint2*)&B_hi[base];
            bl[ni] = *(uint2*)&B_lo[base];
        }
#pragma unroll
        for (int mi = 0; mi < MT; mi++) {
            const uint32_t AH[4] = {ah[mi].x, ah[mi].y, ah[mi].z, ah[mi].w};
            const uint32_t AL[4] = {al[mi].x, al[mi].y, al[mi].z, al[mi].w};
#pragma unroll
            for (int ni = 0; ni < NT; ni++) {
                const uint32_t BH[2] = {bh[ni].x, bh[ni].y};
                const uint32_t BL[2] = {bl[ni].x, bl[ni].y};
                MMA_BF16(acc[mi][ni], AH, BH);
                MMA_BF16(acc[mi][ni], AL, BH);
                MMA_BF16(acc[mi][ni], AH, BL);
            }
        }
    }

    // ---- epilogue ----
#pragma unroll
    for (int mi = 0; mi < MT; mi++) {
        const int rbase = blockRow + wm * RPW + mi * 16;
        const int r0 = rbase + g;
        const int r1 = rbase + g + 8;
#pragma unroll
        for (int ni = 0; ni < NT; ni++) {
            const int col = wn * CPW + ni * 8 + tg * 2;
            if (FINAL) {
                const float2 bb = __ldg((const float2*)(bias + col));
                if (r0 < M)
                    *(float2*)(OUT + (size_t)r0 * TN + col) =
                        make_float2(acc[mi][ni][0] + bb.x, acc[mi][ni][1] + bb.y);
                if (r1 < M)
                    *(float2*)(OUT + (size_t)r1 * TN + col) =
                        make_float2(acc[mi][ni][2] + bb.x, acc[mi][ni][3] + bb.y);
            } else {
                if (r0 < M)
                    *(float2*)(g_s + (size_t)r0 * TN + col) =
                        make_float2(acc[mi][ni][0], acc[mi][ni][1]);
                if (r1 < M)
                    *(float2*)(g_s + (size_t)r1 * TN + col) =
                        make_float2(acc[mi][ni][2], acc[mi][ni][3]);
            }
        }
    }
}

// --------------------------- neighbor aggregation ---------------------------
__global__ __launch_bounds__(256) void aggregate_kernel(
    const float* __restrict__ bias, int n)
{
    const int node = (blockIdx.x * 256 + threadIdx.x) >> 5;
    const int lane = threadIdx.x & 31;
    if (node >= n) return;

    const float dself = __ldg(&g_dinv[node]);
    const float4 sv = __ldg((const float4*)(g_s + (size_t)node * 128) + lane);
    float4 acc = make_float4(dself * sv.x, dself * sv.y,
                             dself * sv.z, dself * sv.w);
    int i = g_off[node];
    const int end = g_off[node + 1];

    for (; i + 4 <= end; i += 4) {
        const int r0 = __ldg(&g_csr[i]);
        const int r1 = __ldg(&g_csr[i + 1]);
        const int r2 = __ldg(&g_csr[i + 2]);
        const int r3 = __ldg(&g_csr[i + 3]);
        const float d0 = __ldg(&g_dinv[r0]);
        const float d1 = __ldg(&g_dinv[r1]);
        const float d2 = __ldg(&g_dinv[r2]);
        const float d3 = __ldg(&g_dinv[r3]);
        const float4 v0 = __ldg((const float4*)(g_s + (size_t)r0 * 128) + lane);
        const float4 v1 = __ldg((const float4*)(g_s + (size_t)r1 * 128) + lane);
        const float4 v2 = __ldg((const float4*)(g_s + (size_t)r2 * 128) + lane);
        const float4 v3 = __ldg((const float4*)(g_s + (size_t)r3 * 128) + lane);
        acc.x = fmaf(d0, v0.x, fmaf(d1, v1.x, fmaf(d2, v2.x, fmaf(d3, v3.x, acc.x))));
        acc.y = fmaf(d0, v0.y, fmaf(d1, v1.y, fmaf(d2, v2.y, fmaf(d3, v3.y, acc.y))));
        acc.z = fmaf(d0, v0.z, fmaf(d1, v1.z, fmaf(d2, v2.z, fmaf(d3, v3.z, acc.z))));
        acc.w = fmaf(d0, v0.w, fmaf(d1, v1.w, fmaf(d2, v2.w, fmaf(d3, v3.w, acc.w))));
    }
    for (; i < end; i++) {
        const int r = __ldg(&g_csr[i]);
        const float d = __ldg(&g_dinv[r]);
        const float4 v = __ldg((const float4*)(g_s + (size_t)r * 128) + lane);
        acc.x = fmaf(d, v.x, acc.x);
        acc.y = fmaf(d, v.y, acc.y);
        acc.z = fmaf(d, v.z, acc.z);
        acc.w = fmaf(d, v.w, acc.w);
    }

    const float4 b = __ldg((const float4*)bias + lane);
    float4 r;
    r.x = fmaxf(fmaf(dself, acc.x, b.x), 0.f);
    r.y = fmaxf(fmaf(dself, acc.y, b.y), 0.f);
    r.z = fmaxf(fmaf(dself, acc.z, b.z), 0.f);
    r.w = fmaxf(fmaf(dself, acc.w, b.w), 0.f);
    *((float4*)(g_h + (size_t)node * 128) + lane) = r;
}

// ------------------------------- launch -------------------------------------
extern "C" void kernel_launch(void* const* d_in, const int* in_sizes, int n_in,
                              void* d_out, int out_size) {
    const float* x  = (const float*)d_in[0];
    const void*  ei =               d_in[1];
    const float* W1 = (const float*)d_in[2];
    const float* b1 = (const float*)d_in[3];
    const float* W2 = (const float*)d_in[4];
    const float* b2 = (const float*)d_in[5];
    const float* Wl = (const float*)d_in[6];
    const float* bl = (const float*)d_in[7];
    float* out = (float*)d_out;

    const int n = in_sizes[0] / 128;   // 50000
    const int E = in_sizes[1] / 2;     // 640000

    float* h_dev = nullptr;  cudaGetSymbolAddress((void**)&h_dev, g_h);

    // SMEM: A 2*8192 words, B 2*(8*NCG*32*2) words
    const int smem128 = (2 * 8192 + 2 * 8192) * 4;   // 131072 B
    const int smem64  = (2 * 8192 + 2 * 4096) * 4;   //  98304 B

    static cudaStream_t s1 = nullptr;
    static cudaEvent_t evFork = nullptr, evJoin = nullptr;
    if (s1 == nullptr) {
        cudaFuncSetAttribute(mma_gemm<128, false>,
                             cudaFuncAttributeMaxDynamicSharedMemorySize, smem128);
        cudaFuncSetAttribute(mma_gemm<64, true>,
                             cudaFuncAttributeMaxDynamicSharedMemorySize, smem64);
        cudaStreamCreateWithFlags(&s1, cudaStreamNonBlocking);
        cudaEventCreateWithFlags(&evFork, cudaEventDisableTiming);
        cudaEventCreateWithFlags(&evJoin, cudaEventDisableTiming);
    }

    const int eB = (E + 255) / 256;
    const int nB = (n + 255) / 256;
    const int sB = (n + SCAN_B - 1) / SCAN_B;
    const int gemmBlocks = (n + 127) / 128;
    const int aggBlocks  = (n * 32 + 255) / 256;

    // ---- fork: layer-1 GEMM (independent of graph prep) on side stream ----
    cudaEventRecord(evFork, 0);
    cudaStreamWaitEvent(s1, evFork, 0);
    mma_gemm<128, false><<<gemmBlocks, 256, smem128, s1>>>(x, W1, nullptr, nullptr, n);
    cudaEventRecord(evJoin, s1);

    // ---- CSR + normalization build on the main stream (overlapped) ----
    zero_detect_kernel<<<nB, 256>>>((const int*)ei, n);
    hist_kernel<<<eB, 256>>>(ei, E);
    scan_blocksum<<<sB, SCAN_B>>>(n);
    scan_final<<<sB, SCAN_B>>>(n);
    fillcsr_kernel<<<eB, 256>>>(ei, E);

    // ---- join, then the serial tail ----
    cudaStreamWaitEvent(0, evJoin, 0);
    aggregate_kernel<<<aggBlocks, 256>>>(b1, n);

    mma_gemm<128, false><<<gemmBlocks, 256, smem128>>>(h_dev, W2, nullptr, nullptr, n);
    aggregate_kernel<<<aggBlocks, 256>>>(b2, n);

    mma_gemm<64, true><<<gemmBlocks, 256, smem64>>>(h_dev, Wl, bl, out, n);
}

// round 17
// speedup vs baseline: 1.0004x; 1.0004x over previous
#include <cuda_runtime.h>
#include <cuda_bf16.h>
#include <cstdint>

// ---------------------------------------------------------------------------
// TrivialGNN: 3-layer GCN.
// Per GCN layer:
//   s = X @ W                     (tensor-core bf16x3 GEMM, unscaled)
//   h[c] = relu( dinv[c] * (dinv[c]*s[c] + sum_{r->c} dinv[r]*s[r]) + b )
// dinv applied during aggregation; layer-1 GEMM overlaps the CSR build on a
// second stream. The dependent tail is HALF-SPLIT pipelined: aggregation of
// one node half overlaps the next GEMM on the other half (double-buffered
// GEMM output g_s/g_s2 removes the WAR hazard). Cross-stream deps via events;
// all work joins the origin stream before capture end.
// CSR build: histogram with rank capture, 2-kernel multi-block scan,
// atomic-free placement.
// ---------------------------------------------------------------------------

#define MAX_N 50000
#define MAX_E 640000
#define SCAN_B 256
#define MAX_SB 256

__device__ float g_dinv[MAX_N];        // rsqrt(in-degree incl. self loop)
__device__ float g_s  [MAX_N * 128];   // XW layer-1 (gather source)
__device__ float g_s2 [MAX_N * 128];   // XW layer-2 (double buffer)
__device__ float g_h  [MAX_N * 128];   // layer output
__device__ int   g_cnt[MAX_N];         // per-destination edge count
__device__ int   g_off[MAX_N + 1];     // CSR offsets
__device__ int   g_rank[MAX_E];        // per-edge rank within its destination
__device__ int   g_csr[MAX_E];         // source node per CSR slot
__device__ int   g_bsum[MAX_SB];       // per-block count sums
__device__ int   g_is64;               // edge_index dtype flag

// ----------------------- zero counts + dtype detect -------------------------
__global__ void zero_detect_kernel(const int* __restrict__ ei, int n) {
    int i = blockIdx.x * blockDim.x + threadIdx.x;
    if (i < n) g_cnt[i] = 0;
    if (blockIdx.x == 0 && threadIdx.x < 32) {
        long long s = 0;
#pragma unroll
        for (int k = 0; k < 32; k++)
            s += (long long)__ldg(ei + 2 * (threadIdx.x * 32 + k) + 1);
#pragma unroll
        for (int o = 16; o > 0; o >>= 1)
            s += __shfl_down_sync(0xffffffffu, s, o);
        if (threadIdx.x == 0) g_is64 = (s == 0) ? 1 : 0;
    }
}

__device__ __forceinline__ void load_edge(const void* ei, int E, int e,
                                          int& r, int& c) {
    if (g_is64) {
        const long long* p = (const long long*)ei;
        r = (int)__ldg(p + e);
        c = (int)__ldg(p + E + e);
    } else {
        const int* p = (const int*)ei;
        r = __ldg(p + e);
        c = __ldg(p + E + e);
    }
}

// ------------------------------ CSR build ----------------------------------
__global__ void hist_kernel(const void* __restrict__ ei, int E) {
    int e = blockIdx.x * blockDim.x + threadIdx.x;
    if (e >= E) return;
    int r, c; load_edge(ei, E, e, r, c);
    g_rank[e] = atomicAdd(&g_cnt[c], 1);
}

// ---- scan phase 1: per-block reduction of counts (+ dinv on the way) ------
__global__ __launch_bounds__(SCAN_B) void scan_blocksum(int n) {
    const int tid  = threadIdx.x;
    const int i    = blockIdx.x * SCAN_B + tid;
    const int lane = tid & 31;
    const int warp = tid >> 5;
    int v = (i < n) ? g_cnt[i] : 0;
    if (i < n) g_dinv[i] = rsqrtf((float)v + 1.0f);   // +1 = self loop
    int s = v;
#pragma unroll
    for (int o = 16; o > 0; o >>= 1) s += __shfl_down_sync(0xffffffffu, s, o);
    __shared__ int sh[SCAN_B / 32];
    if (lane == 0) sh[warp] = s;
    __syncthreads();
    if (tid == 0) {
        int t = 0;
#pragma unroll
        for (int w = 0; w < SCAN_B / 32; w++) t += sh[w];
        g_bsum[blockIdx.x] = t;
    }
}

// ---- scan phase 2 (fused): per-block offset reduce + local exclusive scan --
__global__ __launch_bounds__(SCAN_B) void scan_final(int n) {
    const int tid  = threadIdx.x;
    const int i    = blockIdx.x * SCAN_B + tid;
    const int lane = tid & 31;
    const int warp = tid >> 5;
    __shared__ int shr[SCAN_B / 32];
    __shared__ int shs[SCAN_B / 32];
    __shared__ int boff_s;

    int vb = (tid < blockIdx.x) ? g_bsum[tid] : 0;
#pragma unroll
    for (int o = 16; o > 0; o >>= 1) vb += __shfl_down_sync(0xffffffffu, vb, o);
    if (lane == 0) shr[warp] = vb;
    __syncthreads();
    if (tid == 0) {
        int t = 0;
#pragma unroll
        for (int w = 0; w < SCAN_B / 32; w++) t += shr[w];
        boff_s = t;
    }

    const int v = (i < n) ? g_cnt[i] : 0;
    int x = v;
#pragma unroll
    for (int o = 1; o < 32; o <<= 1) {
        int y = __shfl_up_sync(0xffffffffu, x, o);
        if (lane >= o) x += y;
    }
    if (lane == 31) shs[warp] = x;
    __syncthreads();
    if (tid < SCAN_B / 32) {
        int w = shs[tid];
#pragma unroll
        for (int o = 1; o < SCAN_B / 32; o <<= 1) {
            int y = __shfl_up_sync((1u << (SCAN_B / 32)) - 1u, w, o);
            if (tid >= o) w += y;
        }
        shs[tid] = w;
    }
    __syncthreads();
    const int incl = x + ((warp > 0) ? shs[warp - 1] : 0);
    const int boff = boff_s;
    if (i < n) g_off[i] = boff + incl - v;
    if (blockIdx.x == gridDim.x - 1 && tid == SCAN_B - 1)
        g_off[n] = boff + incl;
}

// Atomic-free placement: pos = off[c] + rank[e].
__global__ void fillcsr_kernel(const void* __restrict__ ei, int E) {
    int e = blockIdx.x * blockDim.x + threadIdx.x;
    if (e >= E) return;
    int r, c; load_edge(ei, E, e, r, c);
    g_csr[g_off[c] + __ldg(&g_rank[e])] = r;
}

// --------------------------- bf16x3 tensor GEMM -----------------------------
__device__ __forceinline__ void pack2(float x, float y,
                                      uint32_t& h, uint32_t& l) {
    __nv_bfloat16 hx = __float2bfloat16_rn(x);
    __nv_bfloat16 hy = __float2bfloat16_rn(y);
    float rx = x - __bfloat162float(hx);
    float ry = y - __bfloat162float(hy);
    __nv_bfloat16 lx = __float2bfloat16_rn(rx);
    __nv_bfloat16 ly = __float2bfloat16_rn(ry);
    h = (uint32_t)*(uint16_t*)&hx | ((uint32_t)*(uint16_t*)&hy << 16);
    l = (uint32_t)*(uint16_t*)&lx | ((uint32_t)*(uint16_t*)&ly << 16);
}

#define MMA_BF16(c, a, b)                                                    \
    asm volatile("mma.sync.aligned.m16n8k16.row.col.f32.bf16.bf16.f32 "      \
                 "{%0,%1,%2,%3}, {%4,%5,%6,%7}, {%8,%9}, {%0,%1,%2,%3};"     \
                 : "+f"((c)[0]), "+f"((c)[1]), "+f"((c)[2]), "+f"((c)[3])    \
                 : "r"((a)[0]), "r"((a)[1]), "r"((a)[2]), "r"((a)[3]),       \
                   "r"((b)[0]), "r"((b)[1]))

// C[rows, TN] = A[rows,128] @ B[128,TN] for rows [rowBase, rowBase+grid*128).
// 128 x TN block tile, 256 threads (8 warps), K=128 staged once in SMEM as
// packed-bf16 hi/lo (row-major, word stride 68 -> conflict-free).
// FINAL=false: OUT[row] = C[row]      FINAL=true: OUT = C + bias
template<int TN, bool FINAL>
__global__ __launch_bounds__(256, 1) void mma_gemm(
    const float* __restrict__ A, const float* __restrict__ B,
    const float* __restrict__ bias, float* __restrict__ OUT,
    int M, int rowBase)
{
    constexpr int WM  = (TN == 128) ? 2 : 4;
    constexpr int WN  = 8 / WM;
    constexpr int MT  = 128 / WM / 16;
    constexpr int NT  = TN / WN / 8;
    constexpr int RPW = 128 / WM;
    constexpr int CPW = TN / WN;
    constexpr int SW  = 68;

    extern __shared__ uint32_t smw[];
    uint32_t* As_hi = smw;
    uint32_t* As_lo = As_hi + 128 * SW;
    uint32_t* Bs_hi = As_lo + 128 * SW;
    uint32_t* Bs_lo = Bs_hi + TN * SW;

    const int tid    = threadIdx.x;
    const int warpId = tid >> 5;
    const int lane   = tid & 31;
    const int g      = lane >> 2;
    const int tg     = lane & 3;
    const int wm     = warpId % WM;
    const int wn     = warpId / WM;
    const int blockRow = rowBase + blockIdx.x * 128;

#pragma unroll
    for (int it = 0; it < 16; it++) {
        const int s   = tid + it * 256;
        const int row = s >> 5;
        const int c4  = (s & 31) << 2;
        float4 v = make_float4(0.f, 0.f, 0.f, 0.f);
        if (blockRow + row < M)
            v = *(const float4*)(A + (size_t)(blockRow + row) * 128 + c4);
        uint32_t h0, l0, h1, l1;
        pack2(v.x, v.y, h0, l0);
        pack2(v.z, v.w, h1, l1);
        const int w = row * SW + ((s & 31) << 1);
        *(uint2*)&As_hi[w] = make_uint2(h0, h1);
        *(uint2*)&As_lo[w] = make_uint2(l0, l1);
    }
#pragma unroll
    for (int it = 0; it < TN / 8; it++) {
        const int s   = tid + it * 256;
        const int col = s & (TN - 1);
        const int kb  = (s / TN) << 2;
        const float b0 = B[(size_t)(kb + 0) * TN + col];
        const float b1 = B[(size_t)(kb + 1) * TN + col];
        const float b2 = B[(size_t)(kb + 2) * TN + col];
        const float b3 = B[(size_t)(kb + 3) * TN + col];
        uint32_t h0, l0, h1, l1;
        pack2(b0, b1, h0, l0);
        pack2(b2, b3, h1, l1);
        const int w = col * SW + (kb >> 1);
        *(uint2*)&Bs_hi[w] = make_uint2(h0, h1);
        *(uint2*)&Bs_lo[w] = make_uint2(l0, l1);
    }
    __syncthreads();

    float acc[MT][NT][4];
#pragma unroll
    for (int mi = 0; mi < MT; mi++)
#pragma unroll
        for (int ni = 0; ni < NT; ni++)
#pragma unroll
            for (int q = 0; q < 4; q++) acc[mi][ni][q] = 0.0f;

#pragma unroll
    for (int kk = 0; kk < 8; kk++) {
        uint32_t ah[MT][4], al[MT][4];
#pragma unroll
        for (int mi = 0; mi < MT; mi++) {
            const int base = (wm * RPW + mi * 16 + g) * SW + kk * 8 + tg;
            ah[mi][0] = As_hi[base];
            ah[mi][1] = As_hi[base + 8 * SW];
            ah[mi][2] = As_hi[base + 4];
            ah[mi][3] = As_hi[base + 8 * SW + 4];
            al[mi][0] = As_lo[base];
            al[mi][1] = As_lo[base + 8 * SW];
            al[mi][2] = As_lo[base + 4];
            al[mi][3] = As_lo[base + 8 * SW + 4];
        }
        uint32_t bh[NT][2], bl[NT][2];
#pragma unroll
        for (int ni = 0; ni < NT; ni++) {
            const int base = (wn * CPW + ni * 8 + g) * SW + kk * 8 + tg;
            bh[ni][0] = Bs_hi[base];
            bh[ni][1] = Bs_hi[base + 4];
            bl[ni][0] = Bs_lo[base];
            bl[ni][1] = Bs_lo[base + 4];
        }
#pragma unroll
        for (int mi = 0; mi < MT; mi++)
#pragma unroll
            for (int ni = 0; ni < NT; ni++) {
                MMA_BF16(acc[mi][ni], ah[mi], bh[ni]);
                MMA_BF16(acc[mi][ni], al[mi], bh[ni]);
                MMA_BF16(acc[mi][ni], ah[mi], bl[ni]);
            }
    }

#pragma unroll
    for (int mi = 0; mi < MT; mi++) {
        const int rbase = blockRow + wm * RPW + mi * 16;
        const int r0 = rbase + g;
        const int r1 = rbase + g + 8;
#pragma unroll
        for (int ni = 0; ni < NT; ni++) {
            const int col = wn * CPW + ni * 8 + tg * 2;
            if (FINAL) {
                const float2 bb = __ldg((const float2*)(bias + col));
                if (r0 < M)
                    *(float2*)(OUT + (size_t)r0 * TN + col) =
                        make_float2(acc[mi][ni][0] + bb.x, acc[mi][ni][1] + bb.y);
                if (r1 < M)
                    *(float2*)(OUT + (size_t)r1 * TN + col) =
                        make_float2(acc[mi][ni][2] + bb.x, acc[mi][ni][3] + bb.y);
            } else {
                if (r0 < M)
                    *(float2*)(OUT + (size_t)r0 * TN + col) =
                        make_float2(acc[mi][ni][0], acc[mi][ni][1]);
                if (r1 < M)
                    *(float2*)(OUT + (size_t)r1 * TN + col) =
                        make_float2(acc[mi][ni][2], acc[mi][ni][3]);
            }
        }
    }
}

// --------------------------- neighbor aggregation ---------------------------
// One warp per node over nodes [base, base+count); gathers from SRC
// (L2-resident), applies dinv per row, writes relu'd g_h once.
__global__ __launch_bounds__(256) void aggregate_kernel(
    const float* __restrict__ SRC, const float* __restrict__ bias,
    int base, int count)
{
    const int idx  = (blockIdx.x * 256 + threadIdx.x) >> 5;
    const int lane = threadIdx.x & 31;
    if (idx >= count) return;
    const int node = base + idx;

    const float dself = __ldg(&g_dinv[node]);
    const float4 sv = __ldg((const float4*)(SRC + (size_t)node * 128) + lane);
    float4 acc = make_float4(dself * sv.x, dself * sv.y,
                             dself * sv.z, dself * sv.w);
    int i = g_off[node];
    const int end = g_off[node + 1];

    for (; i + 4 <= end; i += 4) {
        const int r0 = __ldg(&g_csr[i]);
        const int r1 = __ldg(&g_csr[i + 1]);
        const int r2 = __ldg(&g_csr[i + 2]);
        const int r3 = __ldg(&g_csr[i + 3]);
        const float d0 = __ldg(&g_dinv[r0]);
        const float d1 = __ldg(&g_dinv[r1]);
        const float d2 = __ldg(&g_dinv[r2]);
        const float d3 = __ldg(&g_dinv[r3]);
        const float4 v0 = __ldg((const float4*)(SRC + (size_t)r0 * 128) + lane);
        const float4 v1 = __ldg((const float4*)(SRC + (size_t)r1 * 128) + lane);
        const float4 v2 = __ldg((const float4*)(SRC + (size_t)r2 * 128) + lane);
        const float4 v3 = __ldg((const float4*)(SRC + (size_t)r3 * 128) + lane);
        acc.x = fmaf(d0, v0.x, fmaf(d1, v1.x, fmaf(d2, v2.x, fmaf(d3, v3.x, acc.x))));
        acc.y = fmaf(d0, v0.y, fmaf(d1, v1.y, fmaf(d2, v2.y, fmaf(d3, v3.y, acc.y))));
        acc.z = fmaf(d0, v0.z, fmaf(d1, v1.z, fmaf(d2, v2.z, fmaf(d3, v3.z, acc.z))));
        acc.w = fmaf(d0, v0.w, fmaf(d1, v1.w, fmaf(d2, v2.w, fmaf(d3, v3.w, acc.w))));
    }
    for (; i < end; i++) {
        const int r = __ldg(&g_csr[i]);
        const float d = __ldg(&g_dinv[r]);
        const float4 v = __ldg((const float4*)(SRC + (size_t)r * 128) + lane);
        acc.x = fmaf(d, v.x, acc.x);
        acc.y = fmaf(d, v.y, acc.y);
        acc.z = fmaf(d, v.z, acc.z);
        acc.w = fmaf(d, v.w, acc.w);
    }

    const float4 b = __ldg((const float4*)bias + lane);
    float4 r;
    r.x = fmaxf(fmaf(dself, acc.x, b.x), 0.f);
    r.y = fmaxf(fmaf(dself, acc.y, b.y), 0.f);
    r.z = fmaxf(fmaf(dself, acc.z, b.z), 0.f);
    r.w = fmaxf(fmaf(dself, acc.w, b.w), 0.f);
    *((float4*)(g_h + (size_t)node * 128) + lane) = r;
}

// ------------------------------- launch -------------------------------------
extern "C" void kernel_launch(void* const* d_in, const int* in_sizes, int n_in,
                              void* d_out, int out_size) {
    const float* x  = (const float*)d_in[0];
    const void*  ei =               d_in[1];
    const float* W1 = (const float*)d_in[2];
    const float* b1 = (const float*)d_in[3];
    const float* W2 = (const float*)d_in[4];
    const float* b2 = (const float*)d_in[5];
    const float* Wl = (const float*)d_in[6];
    const float* bl = (const float*)d_in[7];
    float* out = (float*)d_out;

    const int n = in_sizes[0] / 128;   // 50000
    const int E = in_sizes[1] / 2;     // 640000

    float *s_dev = nullptr, *s2_dev = nullptr, *h_dev = nullptr;
    cudaGetSymbolAddress((void**)&s_dev,  g_s);
    cudaGetSymbolAddress((void**)&s2_dev, g_s2);
    cudaGetSymbolAddress((void**)&h_dev,  g_h);

    const int smem128 = (128 * 68 * 2 + 128 * 68 * 2) * 4;   // 139264 B
    const int smem64  = (128 * 68 * 2 +  64 * 68 * 2) * 4;   // 104448 B

    static cudaStream_t s1 = nullptr;
    static cudaEvent_t evFork = nullptr, evJoin = nullptr;
    static cudaEvent_t evA0 = nullptr, evG2a = nullptr;
    static cudaEvent_t evB0 = nullptr, evG3a = nullptr;
    if (s1 == nullptr) {
        cudaFuncSetAttribute(mma_gemm<128, false>,
                             cudaFuncAttributeMaxDynamicSharedMemorySize, smem128);
        cudaFuncSetAttribute(mma_gemm<64, true>,
                             cudaFuncAttributeMaxDynamicSharedMemorySize, smem64);
        cudaStreamCreateWithFlags(&s1, cudaStreamNonBlocking);
        cudaEventCreateWithFlags(&evFork, cudaEventDisableTiming);
        cudaEventCreateWithFlags(&evJoin, cudaEventDisableTiming);
        cudaEventCreateWithFlags(&evA0,   cudaEventDisableTiming);
        cudaEventCreateWithFlags(&evG2a,  cudaEventDisableTiming);
        cudaEventCreateWithFlags(&evB0,   cudaEventDisableTiming);
        cudaEventCreateWithFlags(&evG3a,  cudaEventDisableTiming);
    }

    const int eB = (E + 255) / 256;
    const int nB = (n + 255) / 256;
    const int sB = (n + SCAN_B - 1) / SCAN_B;
    const int gemmBlocks = (n + 127) / 128;

    // Half split, aligned to the 128-row GEMM tile.
    const int H     = (((n + 1) / 2 + 127) / 128) * 128;   // 25088
    const int rows1 = n - H;                               // 24912
    const int gB0   = H / 128;
    const int gB1   = (rows1 + 127) / 128;
    const int aB0   = (H * 32 + 255) / 256;
    const int aB1   = (rows1 * 32 + 255) / 256;

    // ---- fork: layer-1 GEMM (independent of graph prep) on side stream ----
    cudaEventRecord(evFork, 0);
    cudaStreamWaitEvent(s1, evFork, 0);
    mma_gemm<128, false><<<gemmBlocks, 256, smem128, s1>>>(x, W1, nullptr, s_dev, n, 0);
    cudaEventRecord(evJoin, s1);

    // ---- CSR + normalization build on the main stream (overlapped) ----
    zero_detect_kernel<<<nB, 256>>>((const int*)ei, n);
    hist_kernel<<<eB, 256>>>(ei, E);
    scan_blocksum<<<sB, SCAN_B>>>(n);
    scan_final<<<sB, SCAN_B>>>(n);
    fillcsr_kernel<<<eB, 256>>>(ei, E);

    // ---- pipelined tail: half-split agg/gemm overlap ----
    cudaStreamWaitEvent(0, evJoin, 0);

    // agg1 half0, then half1 (main); gemm2 half0 overlaps half1 (s1)
    aggregate_kernel<<<aB0, 256>>>(s_dev, b1, 0, H);
    cudaEventRecord(evA0, 0);
    cudaStreamWaitEvent(s1, evA0, 0);
    mma_gemm<128, false><<<gB0, 256, smem128, s1>>>(h_dev, W2, nullptr, s2_dev, n, 0);
    cudaEventRecord(evG2a, s1);
    aggregate_kernel<<<aB1, 256>>>(s_dev, b1, H, rows1);
    mma_gemm<128, false><<<gB1, 256, smem128>>>(h_dev, W2, nullptr, s2_dev, n, H);

    // agg2 needs ALL of g_s2
    cudaStreamWaitEvent(0, evG2a, 0);
    aggregate_kernel<<<aB0, 256>>>(s2_dev, b2, 0, H);
    cudaEventRecord(evB0, 0);
    cudaStreamWaitEvent(s1, evB0, 0);
    mma_gemm<64, true><<<gB0, 256, smem64, s1>>>(h_dev, Wl, bl, out, n, 0);
    cudaEventRecord(evG3a, s1);
    aggregate_kernel<<<aB1, 256>>>(s2_dev, b2, H, rows1);
    mma_gemm<64, true><<<gB1, 256, smem64>>>(h_dev, Wl, bl, out, n, H);

    // join side stream back into the origin stream before capture ends
    cudaStreamWaitEvent(0, evG3a, 0);
}